// round 17
// baseline (speedup 1.0000x reference)
#include <cuda_runtime.h>
#include <cuda_fp16.h>
#include <cstdint>

// LinearAttentionCell with T=1 reduces algebraically to out = x @ Wv^T.
// R17: R15 skeleton (best: gemm 10.34us, HBM 1725GB/s) with 1.5x more
// concurrent demand -- the single validated positive lever (delivered BW
// rose 1.54->1.73TB/s as in-flight bytes grew). SPLITK 16->32 (KCH=64):
// 512 CTAs, 24KB smem + ~75 regs -> 3 CTAs/SM resident. Split-K atomics hit
// L2-resident out (512KB) so extra splits add ~no DRAM traffic.
// Numerics: single-product fp16, out ~= f16(x)*f16(w), fp32 acc (~2.9e-4).

#define KDIM 2048
#define NDIM 2048
#define MDIM 64
#define NT   128
#define SPLITK 32
#define KCH  64
#define KSTEPS 4      // k16 steps per CTA
#define GT   256      // 8 warps: 2 wm(m32) x 4 wn(n32)

__device__ __forceinline__ uint32_t f16x2(float hi_e, float lo_e) {
    // packs: low 16 = f16(lo_e), high 16 = f16(hi_e)
    uint32_t r;
    asm("cvt.rn.f16x2.f32 %0, %1, %2;" : "=r"(r) : "f"(hi_e), "f"(lo_e));
    return r;
}

__device__ __forceinline__ void mma_f16(float* d, const uint32_t* a,
                                        uint32_t b0, uint32_t b1) {
    asm volatile(
        "mma.sync.aligned.m16n8k16.row.col.f32.f16.f16.f32 "
        "{%0,%1,%2,%3}, {%4,%5,%6,%7}, {%8,%9}, {%0,%1,%2,%3};"
        : "+f"(d[0]), "+f"(d[1]), "+f"(d[2]), "+f"(d[3])
        : "r"(a[0]), "r"(a[1]), "r"(a[2]), "r"(a[3]), "r"(b0), "r"(b1));
}

__device__ __forceinline__ void ldsm4(uint32_t* r, uint32_t addr) {
    asm volatile(
        "ldmatrix.sync.aligned.m8n8.x4.shared.b16 {%0,%1,%2,%3}, [%4];"
        : "=r"(r[0]), "=r"(r[1]), "=r"(r[2]), "=r"(r[3]) : "r"(addr));
}

// swizzled 16B-chunk offset within a [rows x 16k] fp16 tile (pitch 32B)
__device__ __forceinline__ uint32_t swz(int row, int khalf) {
    return (uint32_t)(row * 32 + (((khalf ^ (row >> 2)) & 1) << 4));
}

__global__ __launch_bounds__(GT, 3)
void gemm_kernel(const float* __restrict__ x, const float* __restrict__ Wv,
                 float* __restrict__ out) {
    __shared__ __align__(16) uint8_t AH[KSTEPS][2048];   // x fp16 [64r x 16k]
    __shared__ __align__(16) uint8_t WH[KSTEPS][4096];   // w fp16 [128r x 16k]

    const int tid  = threadIdx.x;
    const int lane = tid & 31;
    const int wid  = tid >> 5;
    const int wm   = wid & 1;      // m32 group 0..1
    const int wn   = wid >> 1;     // n32 group 0..3
    const int g  = lane >> 2;
    const int tt = lane & 3;

    const int n0 = blockIdx.x * NT;
    const int k0 = blockIdx.y * KCH;

    // ---- burst: ALL 12 LDG.128 in flight (4 x-float4 + 8 W-float4) ----
    // idx = i*256 + tid: row = idx>>4, c4 = idx&15 (float4 col in 64-k chunk)
    float4 xr[4], wr[8];
#pragma unroll
    for (int i = 0; i < 4; i++) {
        int idx = i * 256 + tid;
        int row = idx >> 4, c4 = idx & 15;
        xr[i] = *reinterpret_cast<const float4*>(
            x + (size_t)row * KDIM + k0 + c4 * 4);
    }
#pragma unroll
    for (int i = 0; i < 8; i++) {
        int idx = i * 256 + tid;
        int row = idx >> 4, c4 = idx & 15;
        wr[i] = *reinterpret_cast<const float4*>(
            Wv + (size_t)(n0 + row) * KDIM + k0 + c4 * 4);
    }

    // ---- convert + store tiles ----
#pragma unroll
    for (int i = 0; i < 4; i++) {
        int idx = i * 256 + tid;
        int row = idx >> 4, c4 = idx & 15;
        int ks = c4 >> 2, f = (c4 & 3) * 4;
        uint32_t so = swz(row, f >> 3) + ((f & 4) ? 8 : 0);
        uint32_t h01 = f16x2(xr[i].y, xr[i].x);
        uint32_t h23 = f16x2(xr[i].w, xr[i].z);
        *reinterpret_cast<uint2*>(&AH[ks][so]) = make_uint2(h01, h23);
    }
#pragma unroll
    for (int i = 0; i < 8; i++) {
        int idx = i * 256 + tid;
        int row = idx >> 4, c4 = idx & 15;
        int ks = c4 >> 2, f = (c4 & 3) * 4;
        uint32_t so = swz(row, f >> 3) + ((f & 4) ? 8 : 0);
        uint32_t h01 = f16x2(wr[i].y, wr[i].x);
        uint32_t h23 = f16x2(wr[i].w, wr[i].z);
        *reinterpret_cast<uint2*>(&WH[ks][so]) = make_uint2(h01, h23);
    }

    __syncthreads();   // the only barrier

    // ---- ldsm lane offsets (R15-validated) ----
    const int am0 = wm * 32 + (lane & 15);
    const int am1 = am0 + 16;
    const int akh = lane >> 4;
    const uint32_t aoff0 = swz(am0, akh);
    const uint32_t aoff1 = swz(am1, akh);
    const int nl  = ((lane >> 4) & 1) * 8 + (lane & 7);
    const int bkh = (lane >> 3) & 1;
    const uint32_t boff0 = swz(wn * 32 + nl, bkh);
    const uint32_t boff1 = swz(wn * 32 + 16 + nl, bkh);

    float acc[2][4][4];
#pragma unroll
    for (int a = 0; a < 2; a++)
#pragma unroll
        for (int b = 0; b < 4; b++)
#pragma unroll
            for (int c = 0; c < 4; c++) acc[a][b][c] = 0.f;

#pragma unroll
    for (int ks = 0; ks < KSTEPS; ks++) {
        uint32_t a0[4], a1[4], b0[4], b1[4];
        const uint32_t ahb = (uint32_t)__cvta_generic_to_shared(&AH[ks][0]);
        const uint32_t whb = (uint32_t)__cvta_generic_to_shared(&WH[ks][0]);
        ldsm4(a0, ahb + aoff0);
        ldsm4(a1, ahb + aoff1);
        ldsm4(b0, whb + boff0);
        ldsm4(b1, whb + boff1);

        mma_f16(acc[0][0], a0, b0[0], b0[1]);
        mma_f16(acc[0][1], a0, b0[2], b0[3]);
        mma_f16(acc[1][0], a1, b0[0], b0[1]);
        mma_f16(acc[1][1], a1, b0[2], b0[3]);
        mma_f16(acc[0][2], a0, b1[0], b1[1]);
        mma_f16(acc[0][3], a0, b1[2], b1[3]);
        mma_f16(acc[1][2], a1, b1[0], b1[1]);
        mma_f16(acc[1][3], a1, b1[2], b1[3]);
    }

    // ---- epilogue: split-K via vector atomics (L2-resident out) ----
#pragma unroll
    for (int mb = 0; mb < 2; mb++) {
#pragma unroll
        for (int nf = 0; nf < 4; nf++) {
            int m = wm * 32 + mb * 16 + g;
            int n = n0 + wn * 32 + nf * 8 + 2 * tt;
            atomicAdd(reinterpret_cast<float2*>(&out[m * NDIM + n]),
                      make_float2(acc[mb][nf][0], acc[mb][nf][1]));
            atomicAdd(reinterpret_cast<float2*>(&out[(m + 8) * NDIM + n]),
                      make_float2(acc[mb][nf][2], acc[mb][nf][3]));
        }
    }
}

extern "C" void kernel_launch(void* const* d_in, const int* in_sizes, int n_in,
                              void* d_out, int out_size) {
    // inputs: 0=x [64,1,2048] f32, 1=Wq, 2=bq, 3=Wk, 4=bk, 5=Wv [2048,2048], 6=pos
    const float* x  = (const float*)d_in[0];
    const float* Wv = (const float*)d_in[5];
    float* out = (float*)d_out;

    cudaMemsetAsync(out, 0, (size_t)MDIM * NDIM * sizeof(float));
    dim3 grid(NDIM / NT, SPLITK);   // 16 x 32 = 512 CTAs, 3 per SM resident
    gemm_kernel<<<grid, GT>>>(x, Wv, out);

    (void)in_sizes; (void)n_in; (void)out_size;
}